// round 3
// baseline (speedup 1.0000x reference)
#include <cuda_runtime.h>
#include <cuda_bf16.h>
#include <cstdint>

#define N_NODES 100000
#define DIMH 128
#define E_CAP 4000000

// -------- scratch (device globals; no allocation allowed) --------
__device__ __align__(16) float g_aggr[(size_t)N_NODES * DIMH];  // x + sum(neighbors)
__device__ __align__(16) float g_h1[(size_t)N_NODES * DIMH];
__device__ __align__(16) float g_xw[(size_t)N_NODES * DIMH];
__device__ float g_dinv[N_NODES];
__device__ int   g_deg[N_NODES];
__device__ int   g_off[N_NODES + 1];
__device__ int   g_cur[N_NODES];
__device__ int   g_csr[E_CAP];
__device__ int   g_is64;

// -------- packed f32x2 helpers (2x fp32 FMA throughput on sm_103a) --------
__device__ __forceinline__ unsigned long long pack2(float a, float b) {
    unsigned long long r;
    asm("mov.b64 %0, {%1,%2};" : "=l"(r) : "f"(a), "f"(b));
    return r;
}
__device__ __forceinline__ void ffma2(unsigned long long& d, unsigned long long a, unsigned long long b) {
    asm("fma.rn.f32x2 %0, %1, %2, %0;" : "+l"(d) : "l"(a), "l"(b));
}
__device__ __forceinline__ float2 unpack2(unsigned long long v) {
    float2 r;
    asm("mov.b64 {%0,%1}, %2;" : "=f"(r.x), "=f"(r.y) : "l"(v));
    return r;
}

// -------- dtype detection: int64 edge_index has zero odd words --------
__global__ void k_detect(const unsigned int* __restrict__ w) {
    __shared__ int nz;
    if (threadIdx.x == 0) nz = 0;
    __syncthreads();
    if (w[threadIdx.x * 2 + 1] != 0u) atomicOr(&nz, 1);
    __syncthreads();
    if (threadIdx.x == 0) g_is64 = (nz == 0) ? 1 : 0;
}

__device__ __forceinline__ void load_edge(const void* ei, int E, int e, int& s, int& d) {
    if (g_is64) {
        s = (int)__ldg((const long long*)ei + e);
        d = (int)__ldg((const long long*)ei + E + e);
    } else {
        s = __ldg((const int*)ei + e);
        d = __ldg((const int*)ei + E + e);
    }
}

// -------- CSR build --------
__global__ void k_zero_deg() {
    int i = blockIdx.x * 256 + threadIdx.x;
    if (i < N_NODES) g_deg[i] = 0;
}

__global__ __launch_bounds__(256) void k_count(const void* __restrict__ ei, int E) {
    int e = blockIdx.x * 256 + threadIdx.x;
    if (e >= E) return;
    int s, d;
    load_edge(ei, E, e, s, d);
    atomicAdd(&g_deg[d], 1);
}

// single-block exclusive scan over 100k degrees; also computes dinv
__global__ __launch_bounds__(1024) void k_scan() {
    __shared__ int warp_sums[32];
    const int CH = (N_NODES + 1023) / 1024;  // 98
    int t = threadIdx.x;
    int base = t * CH;
    int sum = 0;
    for (int i = 0; i < CH; i++) {
        int idx = base + i;
        if (idx < N_NODES) sum += g_deg[idx];
    }
    int lane = t & 31, wid = t >> 5;
    int v = sum;
#pragma unroll
    for (int o = 1; o < 32; o <<= 1) {
        int u = __shfl_up_sync(~0u, v, o);
        if (lane >= o) v += u;
    }
    if (lane == 31) warp_sums[wid] = v;
    __syncthreads();
    if (wid == 0) {
        int w = warp_sums[lane];
#pragma unroll
        for (int o = 1; o < 32; o <<= 1) {
            int u = __shfl_up_sync(~0u, w, o);
            if (lane >= o) w += u;
        }
        warp_sums[lane] = w;
    }
    __syncthreads();
    int excl = v - sum + ((wid > 0) ? warp_sums[wid - 1] : 0);
    int run = excl;
    for (int i = 0; i < CH; i++) {
        int idx = base + i;
        if (idx < N_NODES) {
            g_off[idx] = run;
            g_cur[idx] = run;
            int dg = g_deg[idx];
            g_dinv[idx] = rsqrtf((float)dg + 1.0f);
            run += dg;
        }
    }
    if (t == 1023) g_off[N_NODES] = run;
}

__global__ __launch_bounds__(256) void k_fill(const void* __restrict__ ei, int E) {
    int e = blockIdx.x * 256 + threadIdx.x;
    if (e >= E) return;
    int s, d;
    load_edge(ei, E, e, s, d);
    int pos = atomicAdd(&g_cur[d], 1);
    g_csr[pos] = s;
}

// -------- GIN gather: aggr[n] = x[n] + sum_{j->n} x[j]  (warp per node) ------
__global__ __launch_bounds__(256) void k_gin_gather(const float* __restrict__ x) {
    int n = blockIdx.x * 8 + (threadIdx.x >> 5);
    if (n >= N_NODES) return;
    int lane = threadIdx.x & 31;
    int beg = g_off[n], end = g_off[n + 1];
    const float4* x4 = (const float4*)x;
    float4 acc = __ldg(x4 + (size_t)n * 32 + lane);  // self term
    int j = beg;
    for (; j + 4 <= end; j += 4) {
        int s0 = __ldg(g_csr + j), s1 = __ldg(g_csr + j + 1);
        int s2 = __ldg(g_csr + j + 2), s3 = __ldg(g_csr + j + 3);
        float4 v0 = __ldg(x4 + (size_t)s0 * 32 + lane);
        float4 v1 = __ldg(x4 + (size_t)s1 * 32 + lane);
        float4 v2 = __ldg(x4 + (size_t)s2 * 32 + lane);
        float4 v3 = __ldg(x4 + (size_t)s3 * 32 + lane);
        acc.x += v0.x + v1.x + v2.x + v3.x;
        acc.y += v0.y + v1.y + v2.y + v3.y;
        acc.z += v0.z + v1.z + v2.z + v3.z;
        acc.w += v0.w + v1.w + v2.w + v3.w;
    }
    for (; j < end; j++) {
        int s = __ldg(g_csr + j);
        float4 v = __ldg(x4 + (size_t)s * 32 + lane);
        acc.x += v.x; acc.y += v.y; acc.z += v.z; acc.w += v.w;
    }
    ((float4*)g_aggr)[(size_t)n * 32 + lane] = acc;
}

// -------- shared-mem row-tile GEMM core: 1 node row x 16 cols per thread ----
__device__ __forceinline__ void gemm_rowtile(const float* __restrict__ inrow,
                                             const float* __restrict__ Ws,
                                             int cg, float o[16]) {
    unsigned long long acc[8];
#pragma unroll
    for (int j = 0; j < 8; j++) acc[j] = 0ULL;
#pragma unroll 4
    for (int k = 0; k < 128; k++) {
        float a = inrow[k];
        unsigned long long a2 = pack2(a, a);
        const ulonglong2* w = (const ulonglong2*)(Ws + k * 128 + cg * 16);
        ulonglong2 p0 = w[0], p1 = w[1], p2 = w[2], p3 = w[3];
        ffma2(acc[0], a2, p0.x); ffma2(acc[1], a2, p0.y);
        ffma2(acc[2], a2, p1.x); ffma2(acc[3], a2, p1.y);
        ffma2(acc[4], a2, p2.x); ffma2(acc[5], a2, p2.y);
        ffma2(acc[6], a2, p3.x); ffma2(acc[7], a2, p3.y);
    }
#pragma unroll
    for (int j = 0; j < 8; j++) {
        float2 f = unpack2(acc[j]);
        o[2 * j] = f.x; o[2 * j + 1] = f.y;
    }
}

// -------- MLP layer 1: h1 = relu(BN(aggr @ W1 + b1)) --------
__global__ __launch_bounds__(256) void k_mlp1(const float* __restrict__ W1,
                                              const float* __restrict__ b1,
                                              const float* __restrict__ gamma,
                                              const float* __restrict__ beta,
                                              const float* __restrict__ rmean,
                                              const float* __restrict__ rvar) {
    extern __shared__ float sm[];
    float* Ws = sm;                  // 16384
    float* ins = Ws + 16384;         // 32*129
    float* scale_s = ins + 4128;     // 128
    float* shift_s = scale_s + 128;  // 128
    int tid = threadIdx.x;

    const float4* W4 = (const float4*)W1;
    float4* Ws4 = (float4*)Ws;
    for (int i = tid; i < 4096; i += 256) Ws4[i] = W4[i];
    if (tid < 128) {
        float sc = gamma[tid] * rsqrtf(rvar[tid] + 1e-5f);
        scale_s[tid] = sc;
        shift_s[tid] = (b1[tid] - rmean[tid]) * sc + beta[tid];
    }
    int node0 = blockIdx.x << 5;
    for (int i = tid; i < 1024; i += 256) {
        int n = i >> 5, q = i & 31;
        float4 a = ((const float4*)g_aggr)[(size_t)(node0 + n) * 32 + q];
        float* p = ins + n * 129 + q * 4;
        p[0] = a.x; p[1] = a.y; p[2] = a.z; p[3] = a.w;
    }
    __syncthreads();

    int nl = tid >> 3, cg = tid & 7;
    float o[16];
    gemm_rowtile(ins + nl * 129, Ws, cg, o);

    int node = node0 + nl;
    float2* hp = (float2*)g_h1 + (size_t)node * 64 + cg * 8;
#pragma unroll
    for (int j = 0; j < 8; j++) {
        int c = cg * 16 + 2 * j;
        float v0 = fmaxf(o[2 * j] * scale_s[c] + shift_s[c], 0.f);
        float v1 = fmaxf(o[2 * j + 1] * scale_s[c + 1] + shift_s[c + 1], 0.f);
        hp[j] = make_float2(v0, v1);
    }
}

// -------- MLP layer 2 + fused dual-GCN projection --------
__global__ __launch_bounds__(256) void k_mlp2(const float* __restrict__ W2,
                                              const float* __restrict__ b2,
                                              const float* __restrict__ Wmu,
                                              const float* __restrict__ bmu,
                                              const float* __restrict__ Wls,
                                              const float* __restrict__ bls,
                                              float* __restrict__ out) {
    extern __shared__ float sm[];
    float* W2s = sm;               // 16384
    float* Wcs = W2s + 16384;      // 16384
    float* ins = Wcs + 16384;      // 4128
    float* h2s = ins + 4128;       // 4128
    float* b2s = h2s + 4128;       // 128
    float* bcs = b2s + 128;        // 128
    int tid = threadIdx.x;

    float4* W2s4 = (float4*)W2s;
    const float4* W24 = (const float4*)W2;
    for (int i = tid; i < 4096; i += 256) W2s4[i] = W24[i];
    float4* Wcs4 = (float4*)Wcs;
    const float4* Wmu4 = (const float4*)Wmu;
    const float4* Wls4 = (const float4*)Wls;
    for (int i = tid; i < 2048; i += 256) {
        int k = i >> 4, q = i & 15;
        Wcs4[k * 32 + q] = Wmu4[i];
        Wcs4[k * 32 + 16 + q] = Wls4[i];
    }
    if (tid < 128) {
        b2s[tid] = b2[tid];
        bcs[tid] = (tid < 64) ? bmu[tid] : bls[tid - 64];
    }
    int node0 = blockIdx.x << 5;
    for (int i = tid; i < 1024; i += 256) {
        int n = i >> 5, q = i & 31;
        float4 a = ((const float4*)g_h1)[(size_t)(node0 + n) * 32 + q];
        float* p = ins + n * 129 + q * 4;
        p[0] = a.x; p[1] = a.y; p[2] = a.z; p[3] = a.w;
    }
    __syncthreads();

    int nl = tid >> 3, cg = tid & 7;
    float o[16];
    gemm_rowtile(ins + nl * 129, W2s, cg, o);
    {
        float* hp = h2s + nl * 129 + cg * 16;
#pragma unroll
        for (int j = 0; j < 16; j++) {
            int c = cg * 16 + j;
            hp[j] = fmaxf(o[j] + b2s[c], 0.f);
        }
    }
    __syncthreads();
    gemm_rowtile(h2s + nl * 129, Wcs, cg, o);

    int node = node0 + nl;
    float di = g_dinv[node];
    float d2 = di * di;
    float2* xp = (float2*)g_xw + (size_t)node * 64 + cg * 8;
    float* ob = (cg < 4)
        ? (out + (size_t)node * 64 + cg * 16)
        : (out + (size_t)N_NODES * 64 + (size_t)node * 64 + (cg - 4) * 16);
#pragma unroll
    for (int j = 0; j < 8; j++) {
        int c = cg * 16 + 2 * j;
        float x0 = o[2 * j], x1 = o[2 * j + 1];
        xp[j] = make_float2(x0, x1);
        ((float2*)ob)[j] = make_float2(x0 * d2 + bcs[c], x1 * d2 + bcs[c + 1]);
    }
}

// -------- GCN gather: out[n] += dinv[n] * sum dinv[s]*xw[s]  (warp/node) ----
__global__ __launch_bounds__(256) void k_gcn_gather(float* __restrict__ out) {
    int n = blockIdx.x * 8 + (threadIdx.x >> 5);
    if (n >= N_NODES) return;
    int lane = threadIdx.x & 31;
    int beg = g_off[n], end = g_off[n + 1];
    const float4* xw4 = (const float4*)g_xw;
    float4 acc = make_float4(0.f, 0.f, 0.f, 0.f);
    int j = beg;
    for (; j + 4 <= end; j += 4) {
        int s0 = __ldg(g_csr + j), s1 = __ldg(g_csr + j + 1);
        int s2 = __ldg(g_csr + j + 2), s3 = __ldg(g_csr + j + 3);
        float w0 = g_dinv[s0], w1 = g_dinv[s1], w2 = g_dinv[s2], w3 = g_dinv[s3];
        float4 v0 = __ldg(xw4 + (size_t)s0 * 32 + lane);
        float4 v1 = __ldg(xw4 + (size_t)s1 * 32 + lane);
        float4 v2 = __ldg(xw4 + (size_t)s2 * 32 + lane);
        float4 v3 = __ldg(xw4 + (size_t)s3 * 32 + lane);
        acc.x += w0 * v0.x + w1 * v1.x + w2 * v2.x + w3 * v3.x;
        acc.y += w0 * v0.y + w1 * v1.y + w2 * v2.y + w3 * v3.y;
        acc.z += w0 * v0.z + w1 * v1.z + w2 * v2.z + w3 * v3.z;
        acc.w += w0 * v0.w + w1 * v1.w + w2 * v2.w + w3 * v3.w;
    }
    for (; j < end; j++) {
        int s = __ldg(g_csr + j);
        float w = g_dinv[s];
        float4 v = __ldg(xw4 + (size_t)s * 32 + lane);
        acc.x += w * v.x; acc.y += w * v.y; acc.z += w * v.z; acc.w += w * v.w;
    }
    float dn = g_dinv[n];
    int c0 = lane * 4;
    float* ob = (c0 < 64)
        ? (out + (size_t)n * 64 + c0)
        : (out + (size_t)N_NODES * 64 + (size_t)n * 64 + (c0 - 64));
    float4 cur = *(float4*)ob;  // self-loop term + bias (written by k_mlp2)
    cur.x += dn * acc.x; cur.y += dn * acc.y;
    cur.z += dn * acc.z; cur.w += dn * acc.w;
    *(float4*)ob = cur;
}

extern "C" void kernel_launch(void* const* d_in, const int* in_sizes, int n_in,
                              void* d_out, int out_size) {
    const float* x        = (const float*)d_in[0];
    const void*  ei       = (const void*)d_in[1];
    const float* W1       = (const float*)d_in[2];
    const float* b1       = (const float*)d_in[3];
    const float* gamma    = (const float*)d_in[4];
    const float* beta     = (const float*)d_in[5];
    const float* rmean    = (const float*)d_in[6];
    const float* rvar     = (const float*)d_in[7];
    const float* W2       = (const float*)d_in[8];
    const float* b2       = (const float*)d_in[9];
    const float* Wmu      = (const float*)d_in[10];
    const float* bmu      = (const float*)d_in[11];
    const float* Wls      = (const float*)d_in[12];
    const float* bls      = (const float*)d_in[13];
    float* out = (float*)d_out;

    int E = in_sizes[1] / 2;

    const int SMEM1 = (16384 + 4128 + 256) * 4;            // 83072 B
    const int SMEM2 = (16384 * 2 + 4128 * 2 + 256) * 4;    // 165120 B
    cudaFuncSetAttribute(k_mlp1, cudaFuncAttributeMaxDynamicSharedMemorySize, SMEM1);
    cudaFuncSetAttribute(k_mlp2, cudaFuncAttributeMaxDynamicSharedMemorySize, SMEM2);

    int eb = (E + 255) / 256;
    int nb = (N_NODES + 7) / 8;

    k_detect<<<1, 256>>>((const unsigned int*)ei);
    k_zero_deg<<<(N_NODES + 255) / 256, 256>>>();
    k_count<<<eb, 256>>>(ei, E);
    k_scan<<<1, 1024>>>();
    k_fill<<<eb, 256>>>(ei, E);
    k_gin_gather<<<nb, 256>>>(x);
    k_mlp1<<<N_NODES / 32, 256, SMEM1>>>(W1, b1, gamma, beta, rmean, rvar);
    k_mlp2<<<N_NODES / 32, 256, SMEM2>>>(W2, b2, Wmu, bmu, Wls, bls, out);
    k_gcn_gather<<<nb, 256>>>(out);
}

// round 4
// speedup vs baseline: 2.9348x; 2.9348x over previous
#include <cuda_runtime.h>
#include <cstdint>

#define N_NODES 100000
#define DIMH 128
#define E_CAP 4000000

// -------- scratch (device globals; no allocation allowed) --------
__device__ __align__(16) float g_aggr[(size_t)N_NODES * DIMH];
__device__ __align__(16) float g_h1[(size_t)N_NODES * DIMH];
__device__ __align__(16) float g_xw[(size_t)N_NODES * DIMH];   // dinv-scaled xw
__device__ float g_dinv[N_NODES];
__device__ int   g_deg[N_NODES];
__device__ int   g_off[N_NODES + 1];
__device__ int   g_cur[N_NODES];
__device__ int   g_csr[E_CAP];
__device__ int2  g_edge[E_CAP];

// -------- packed f32x2 helpers --------
__device__ __forceinline__ unsigned long long pack2(float a, float b) {
    unsigned long long r;
    asm("mov.b64 %0, {%1,%2};" : "=l"(r) : "f"(a), "f"(b));
    return r;
}
__device__ __forceinline__ void ffma2(unsigned long long& d, unsigned long long a, unsigned long long b) {
    asm("fma.rn.f32x2 %0, %1, %2, %0;" : "+l"(d) : "l"(a), "l"(b));
}
__device__ __forceinline__ float2 unpack2(unsigned long long v) {
    float2 r;
    asm("mov.b64 {%0,%1}, %2;" : "=f"(r.x), "=f"(r.y) : "l"(v));
    return r;
}

// -------- zero deg --------
__global__ void k_zero() {
    int i = blockIdx.x * 256 + threadIdx.x;
    if (i < N_NODES) g_deg[i] = 0;
}

// -------- count + edge conversion (per-block dtype detect) --------
__global__ __launch_bounds__(256) void k_count(const void* __restrict__ ei, int E) {
    __shared__ int s_is64;
    if (threadIdx.x < 32) {
        unsigned w = __ldg((const unsigned*)ei + threadIdx.x * 2 + 1);
        unsigned b = __ballot_sync(0xffffffffu, w != 0u);
        if (threadIdx.x == 0) s_is64 = (b == 0u);
    }
    __syncthreads();
    int e = blockIdx.x * 256 + threadIdx.x;
    if (e >= E) return;
    int s, d;
    if (s_is64) {
        s = (int)__ldg((const long long*)ei + e);
        d = (int)__ldg((const long long*)ei + E + e);
    } else {
        s = __ldg((const int*)ei + e);
        d = __ldg((const int*)ei + E + e);
    }
    g_edge[e] = make_int2(s, d);
    atomicAdd(&g_deg[d], 1);
}

// -------- coalesced tiled single-block scan (+ dinv) --------
__global__ __launch_bounds__(1024) void k_scan() {
    __shared__ int wsum[32];
    __shared__ int s_carry;
    int tid = threadIdx.x, lane = tid & 31, wid = tid >> 5;
    if (tid == 0) s_carry = 0;
    __syncthreads();
    const int NT = (N_NODES + 1023) / 1024;  // 98
    for (int t = 0; t < NT; t++) {
        int idx = t * 1024 + tid;
        int dg = (idx < N_NODES) ? g_deg[idx] : 0;
        int v = dg;
#pragma unroll
        for (int o = 1; o < 32; o <<= 1) {
            int u = __shfl_up_sync(~0u, v, o);
            if (lane >= o) v += u;
        }
        if (lane == 31) wsum[wid] = v;
        __syncthreads();
        if (wid == 0) {
            int w = wsum[lane];
#pragma unroll
            for (int o = 1; o < 32; o <<= 1) {
                int u = __shfl_up_sync(~0u, w, o);
                if (lane >= o) w += u;
            }
            wsum[lane] = w;
        }
        __syncthreads();
        int excl = v - dg + ((wid > 0) ? wsum[wid - 1] : 0) + s_carry;
        if (idx < N_NODES) {
            g_off[idx] = excl;
            g_cur[idx] = excl;
            g_dinv[idx] = rsqrtf((float)dg + 1.0f);
        }
        __syncthreads();
        if (tid == 0) s_carry += wsum[31];
        __syncthreads();
    }
    if (tid == 0) g_off[N_NODES] = s_carry;
}

// -------- fill CSR --------
__global__ __launch_bounds__(256) void k_fill(int E) {
    int e = blockIdx.x * 256 + threadIdx.x;
    if (e >= E) return;
    int2 sd = g_edge[e];
    int pos = atomicAdd(&g_cur[sd.y], 1);
    g_csr[pos] = sd.x;
}

// -------- GIN gather: aggr[n] = x[n] + sum x[csr]  (warp/node, 8-deep) -----
__global__ __launch_bounds__(256) void k_gin_gather(const float* __restrict__ x) {
    int n = blockIdx.x * 8 + (threadIdx.x >> 5);
    if (n >= N_NODES) return;
    int lane = threadIdx.x & 31;
    int beg = __ldg(g_off + n), end = __ldg(g_off + n + 1);
    const float4* x4 = (const float4*)x;
    float4 acc = __ldg(x4 + (size_t)n * 32 + lane);
    int j = beg;
    for (; j + 8 <= end; j += 8) {
        int idx[8];
#pragma unroll
        for (int t = 0; t < 8; t++) idx[t] = __ldg(g_csr + j + t);
        float4 v[8];
#pragma unroll
        for (int t = 0; t < 8; t++) v[t] = __ldg(x4 + (size_t)idx[t] * 32 + lane);
#pragma unroll
        for (int t = 0; t < 8; t++) {
            acc.x += v[t].x; acc.y += v[t].y; acc.z += v[t].z; acc.w += v[t].w;
        }
    }
    for (; j < end; j++) {
        int s = __ldg(g_csr + j);
        float4 v = __ldg(x4 + (size_t)s * 32 + lane);
        acc.x += v.x; acc.y += v.y; acc.z += v.z; acc.w += v.w;
    }
    ((float4*)g_aggr)[(size_t)n * 32 + lane] = acc;
}

// -------- conflict-free GEMM core --------
// thread owns cols {cg*4 + 32*m + j : m=0..3, j=0..3}; o[4*m+j]
__device__ __forceinline__ void gemm_rowtile(const float* __restrict__ inrow,
                                             const float* __restrict__ Ws,
                                             int cg, float o[16]) {
    unsigned long long acc[8];
#pragma unroll
    for (int j = 0; j < 8; j++) acc[j] = 0ULL;
#pragma unroll 4
    for (int k = 0; k < 128; k++) {
        float a = inrow[k];
        unsigned long long a2 = pack2(a, a);
#pragma unroll
        for (int m = 0; m < 4; m++) {
            ulonglong2 w = *(const ulonglong2*)(Ws + k * 128 + cg * 4 + 32 * m);
            ffma2(acc[2 * m], a2, w.x);
            ffma2(acc[2 * m + 1], a2, w.y);
        }
    }
#pragma unroll
    for (int m = 0; m < 4; m++) {
        float2 f0 = unpack2(acc[2 * m]);
        float2 f1 = unpack2(acc[2 * m + 1]);
        o[4 * m + 0] = f0.x; o[4 * m + 1] = f0.y;
        o[4 * m + 2] = f1.x; o[4 * m + 3] = f1.y;
    }
}

// load 32 node rows (128 f) into smem with 129 pad
__device__ __forceinline__ void load_rows(const float* __restrict__ src, int node0,
                                          float* __restrict__ ins, int tid) {
    for (int i = tid; i < 1024; i += 256) {
        int n = i >> 5, q = i & 31;
        float4 a = __ldg((const float4*)src + (size_t)(node0 + n) * 32 + q);
        float* p = ins + n * 129 + q * 4;
        p[0] = a.x; p[1] = a.y; p[2] = a.z; p[3] = a.w;
    }
}

// -------- MLP1: h1 = relu(BN(aggr @ W1)) --------
__global__ __launch_bounds__(256) void k_mlp1(const float* __restrict__ W1,
                                              const float* __restrict__ b1,
                                              const float* __restrict__ gamma,
                                              const float* __restrict__ beta,
                                              const float* __restrict__ rmean,
                                              const float* __restrict__ rvar) {
    extern __shared__ float sm[];
    float* Ws = sm;                  // 16384
    float* ins = Ws + 16384;         // 4128
    float* scale_s = ins + 4128;     // 128
    float* shift_s = scale_s + 128;  // 128
    int tid = threadIdx.x;
    for (int i = tid; i < 4096; i += 256) ((float4*)Ws)[i] = __ldg((const float4*)W1 + i);
    if (tid < 128) {
        float sc = gamma[tid] * rsqrtf(rvar[tid] + 1e-5f);
        scale_s[tid] = sc;
        shift_s[tid] = (b1[tid] - rmean[tid]) * sc + beta[tid];
    }
    int node0 = blockIdx.x << 5;
    load_rows(g_aggr, node0, ins, tid);
    __syncthreads();

    int nl = tid >> 3, cg = tid & 7;
    float o[16];
    gemm_rowtile(ins + nl * 129, Ws, cg, o);
    int node = node0 + nl;
#pragma unroll
    for (int m = 0; m < 4; m++) {
        int c0 = cg * 4 + 32 * m;
        float4 r;
        r.x = fmaxf(o[4 * m + 0] * scale_s[c0 + 0] + shift_s[c0 + 0], 0.f);
        r.y = fmaxf(o[4 * m + 1] * scale_s[c0 + 1] + shift_s[c0 + 1], 0.f);
        r.z = fmaxf(o[4 * m + 2] * scale_s[c0 + 2] + shift_s[c0 + 2], 0.f);
        r.w = fmaxf(o[4 * m + 3] * scale_s[c0 + 3] + shift_s[c0 + 3], 0.f);
        *(float4*)(g_h1 + (size_t)node * 128 + c0) = r;
    }
}

// -------- MLP2: h2 = relu(h1 @ W2 + b2), in place --------
__global__ __launch_bounds__(256) void k_mlp2(const float* __restrict__ W2,
                                              const float* __restrict__ b2) {
    extern __shared__ float sm[];
    float* Ws = sm;
    float* ins = Ws + 16384;
    float* bs = ins + 4128;
    int tid = threadIdx.x;
    for (int i = tid; i < 4096; i += 256) ((float4*)Ws)[i] = __ldg((const float4*)W2 + i);
    if (tid < 128) bs[tid] = b2[tid];
    int node0 = blockIdx.x << 5;
    load_rows(g_h1, node0, ins, tid);
    __syncthreads();

    int nl = tid >> 3, cg = tid & 7;
    float o[16];
    gemm_rowtile(ins + nl * 129, Ws, cg, o);
    int node = node0 + nl;
#pragma unroll
    for (int m = 0; m < 4; m++) {
        int c0 = cg * 4 + 32 * m;
        float4 r;
        r.x = fmaxf(o[4 * m + 0] + bs[c0 + 0], 0.f);
        r.y = fmaxf(o[4 * m + 1] + bs[c0 + 1], 0.f);
        r.z = fmaxf(o[4 * m + 2] + bs[c0 + 2], 0.f);
        r.w = fmaxf(o[4 * m + 3] + bs[c0 + 3], 0.f);
        *(float4*)(g_h1 + (size_t)node * 128 + c0) = r;
    }
}

// -------- MLP3: xw = h2 @ [Wmu|Wls]; store xws = dinv*xw; out = dinv*xws + b --
__global__ __launch_bounds__(256) void k_mlp3(const float* __restrict__ Wmu,
                                              const float* __restrict__ bmu,
                                              const float* __restrict__ Wls,
                                              const float* __restrict__ bls,
                                              float* __restrict__ out) {
    extern __shared__ float sm[];
    float* Ws = sm;
    float* ins = Ws + 16384;
    float* bs = ins + 4128;
    int tid = threadIdx.x;
    for (int i = tid; i < 4096; i += 256) {
        int k = i >> 5, q = i & 31;
        float4 v = (q < 16) ? __ldg((const float4*)Wmu + k * 16 + q)
                            : __ldg((const float4*)Wls + k * 16 + (q - 16));
        ((float4*)Ws)[i] = v;
    }
    if (tid < 128) bs[tid] = (tid < 64) ? bmu[tid] : bls[tid - 64];
    int node0 = blockIdx.x << 5;
    load_rows(g_h1, node0, ins, tid);
    __syncthreads();

    int nl = tid >> 3, cg = tid & 7;
    float o[16];
    gemm_rowtile(ins + nl * 129, Ws, cg, o);
    int node = node0 + nl;
    float dn = g_dinv[node];
#pragma unroll
    for (int m = 0; m < 4; m++) {
        int c0 = cg * 4 + 32 * m;
        float4 xs;
        xs.x = dn * o[4 * m + 0]; xs.y = dn * o[4 * m + 1];
        xs.z = dn * o[4 * m + 2]; xs.w = dn * o[4 * m + 3];
        *(float4*)(g_xw + (size_t)node * 128 + c0) = xs;
        float4 ov;
        ov.x = dn * xs.x + bs[c0 + 0];
        ov.y = dn * xs.y + bs[c0 + 1];
        ov.z = dn * xs.z + bs[c0 + 2];
        ov.w = dn * xs.w + bs[c0 + 3];
        float* ob = (c0 < 64) ? (out + (size_t)node * 64 + c0)
                              : (out + (size_t)N_NODES * 64 + (size_t)node * 64 + (c0 - 64));
        *(float4*)ob = ov;
    }
}

// -------- GCN gather: out[n] += dinv[n] * sum xws[csr]  (warp/node, 8-deep) --
__global__ __launch_bounds__(256) void k_gcn_gather(float* __restrict__ out) {
    int n = blockIdx.x * 8 + (threadIdx.x >> 5);
    if (n >= N_NODES) return;
    int lane = threadIdx.x & 31;
    int beg = __ldg(g_off + n), end = __ldg(g_off + n + 1);
    const float4* xw4 = (const float4*)g_xw;
    float4 acc = make_float4(0.f, 0.f, 0.f, 0.f);
    int j = beg;
    for (; j + 8 <= end; j += 8) {
        int idx[8];
#pragma unroll
        for (int t = 0; t < 8; t++) idx[t] = __ldg(g_csr + j + t);
        float4 v[8];
#pragma unroll
        for (int t = 0; t < 8; t++) v[t] = __ldg(xw4 + (size_t)idx[t] * 32 + lane);
#pragma unroll
        for (int t = 0; t < 8; t++) {
            acc.x += v[t].x; acc.y += v[t].y; acc.z += v[t].z; acc.w += v[t].w;
        }
    }
    for (; j < end; j++) {
        int s = __ldg(g_csr + j);
        float4 v = __ldg(xw4 + (size_t)s * 32 + lane);
        acc.x += v.x; acc.y += v.y; acc.z += v.z; acc.w += v.w;
    }
    float dn = g_dinv[n];
    int c0 = lane * 4;
    float* ob = (c0 < 64) ? (out + (size_t)n * 64 + c0)
                          : (out + (size_t)N_NODES * 64 + (size_t)n * 64 + (c0 - 64));
    float4 cur = *(float4*)ob;
    cur.x += dn * acc.x; cur.y += dn * acc.y;
    cur.z += dn * acc.z; cur.w += dn * acc.w;
    *(float4*)ob = cur;
}

extern "C" void kernel_launch(void* const* d_in, const int* in_sizes, int n_in,
                              void* d_out, int out_size) {
    const float* x     = (const float*)d_in[0];
    const void*  ei    = (const void*)d_in[1];
    const float* W1    = (const float*)d_in[2];
    const float* b1    = (const float*)d_in[3];
    const float* gamma = (const float*)d_in[4];
    const float* beta  = (const float*)d_in[5];
    const float* rmean = (const float*)d_in[6];
    const float* rvar  = (const float*)d_in[7];
    const float* W2    = (const float*)d_in[8];
    const float* b2    = (const float*)d_in[9];
    const float* Wmu   = (const float*)d_in[10];
    const float* bmu   = (const float*)d_in[11];
    const float* Wls   = (const float*)d_in[12];
    const float* bls   = (const float*)d_in[13];
    float* out = (float*)d_out;

    int E = in_sizes[1] / 2;

    const int SMEM = (16384 + 4128 + 256) * 4;  // 83072 B
    cudaFuncSetAttribute(k_mlp1, cudaFuncAttributeMaxDynamicSharedMemorySize, SMEM);
    cudaFuncSetAttribute(k_mlp2, cudaFuncAttributeMaxDynamicSharedMemorySize, SMEM);
    cudaFuncSetAttribute(k_mlp3, cudaFuncAttributeMaxDynamicSharedMemorySize, SMEM);

    int eb = (E + 255) / 256;
    int nb = (N_NODES + 7) / 8;

    k_zero<<<(N_NODES + 255) / 256, 256>>>();
    k_count<<<eb, 256>>>(ei, E);
    k_scan<<<1, 1024>>>();
    k_fill<<<eb, 256>>>(E);
    k_gin_gather<<<nb, 256>>>(x);
    k_mlp1<<<N_NODES / 32, 256, SMEM>>>(W1, b1, gamma, beta, rmean, rvar);
    k_mlp2<<<N_NODES / 32, 256, SMEM>>>(W2, b2);
    k_mlp3<<<N_NODES / 32, 256, SMEM>>>(Wmu, bmu, Wls, bls, out);
    k_gcn_gather<<<nb, 256>>>(out);
}

// round 5
// speedup vs baseline: 4.0887x; 1.3932x over previous
#include <cuda_runtime.h>
#include <cstdint>

#define N_NODES 100000
#define DIMH 128
#define E_CAP 4000000

// -------- scratch (device globals; no allocation allowed) --------
__device__ __align__(16) float g_aggr[(size_t)N_NODES * DIMH];
__device__ __align__(16) float g_h1[(size_t)N_NODES * DIMH];
__device__ __align__(16) float g_xw[(size_t)N_NODES * DIMH];   // dinv-scaled xw
__device__ float g_dinv[N_NODES];
__device__ int   g_deg[N_NODES];
__device__ int   g_off[N_NODES + 1];
__device__ int   g_cur[N_NODES];
__device__ int   g_csr[E_CAP];
__device__ int2  g_edge[E_CAP];

// -------- packed f32x2 helpers --------
__device__ __forceinline__ unsigned long long pack2(float a, float b) {
    unsigned long long r;
    asm("mov.b64 %0, {%1,%2};" : "=l"(r) : "f"(a), "f"(b));
    return r;
}
__device__ __forceinline__ void ffma2(unsigned long long& d, unsigned long long a, unsigned long long b) {
    asm("fma.rn.f32x2 %0, %1, %2, %0;" : "+l"(d) : "l"(a), "l"(b));
}
__device__ __forceinline__ float2 unpack2(unsigned long long v) {
    float2 r;
    asm("mov.b64 {%0,%1}, %2;" : "=f"(r.x), "=f"(r.y) : "l"(v));
    return r;
}

// -------- zero deg --------
__global__ void k_zero() {
    int i = blockIdx.x * 256 + threadIdx.x;
    if (i < N_NODES) g_deg[i] = 0;
}

// -------- count + edge conversion (per-block dtype detect) --------
__global__ __launch_bounds__(256) void k_count(const void* __restrict__ ei, int E) {
    __shared__ int s_is64;
    if (threadIdx.x < 32) {
        unsigned w = __ldg((const unsigned*)ei + threadIdx.x * 2 + 1);
        unsigned b = __ballot_sync(0xffffffffu, w != 0u);
        if (threadIdx.x == 0) s_is64 = (b == 0u);
    }
    __syncthreads();
    int e = blockIdx.x * 256 + threadIdx.x;
    if (e >= E) return;
    int s, d;
    if (s_is64) {
        s = (int)__ldg((const long long*)ei + e);
        d = (int)__ldg((const long long*)ei + E + e);
    } else {
        s = __ldg((const int*)ei + e);
        d = __ldg((const int*)ei + E + e);
    }
    g_edge[e] = make_int2(s, d);
    atomicAdd(&g_deg[d], 1);
}

// -------- coalesced tiled single-block scan (+ dinv) --------
__global__ __launch_bounds__(1024) void k_scan() {
    __shared__ int wsum[32];
    __shared__ int s_carry;
    int tid = threadIdx.x, lane = tid & 31, wid = tid >> 5;
    if (tid == 0) s_carry = 0;
    __syncthreads();
    const int NT = (N_NODES + 1023) / 1024;  // 98
    for (int t = 0; t < NT; t++) {
        int idx = t * 1024 + tid;
        int dg = (idx < N_NODES) ? g_deg[idx] : 0;
        int v = dg;
#pragma unroll
        for (int o = 1; o < 32; o <<= 1) {
            int u = __shfl_up_sync(~0u, v, o);
            if (lane >= o) v += u;
        }
        if (lane == 31) wsum[wid] = v;
        __syncthreads();
        if (wid == 0) {
            int w = wsum[lane];
#pragma unroll
            for (int o = 1; o < 32; o <<= 1) {
                int u = __shfl_up_sync(~0u, w, o);
                if (lane >= o) w += u;
            }
            wsum[lane] = w;
        }
        __syncthreads();
        int excl = v - dg + ((wid > 0) ? wsum[wid - 1] : 0) + s_carry;
        if (idx < N_NODES) {
            g_off[idx] = excl;
            g_cur[idx] = excl;
            g_dinv[idx] = rsqrtf((float)dg + 1.0f);
        }
        __syncthreads();
        if (tid == 0) s_carry += wsum[31];
        __syncthreads();
    }
    if (tid == 0) g_off[N_NODES] = s_carry;
}

// -------- fill CSR --------
__global__ __launch_bounds__(256) void k_fill(int E) {
    int e = blockIdx.x * 256 + threadIdx.x;
    if (e >= E) return;
    int2 sd = g_edge[e];
    int pos = atomicAdd(&g_cur[sd.y], 1);
    g_csr[pos] = sd.x;
}

// -------- GIN gather: aggr[n] = x[n] + sum x[csr]  (warp/node, 8-deep) -----
__global__ __launch_bounds__(256) void k_gin_gather(const float* __restrict__ x) {
    int n = blockIdx.x * 8 + (threadIdx.x >> 5);
    if (n >= N_NODES) return;
    int lane = threadIdx.x & 31;
    int beg = __ldg(g_off + n), end = __ldg(g_off + n + 1);
    const float4* x4 = (const float4*)x;
    float4 acc = __ldg(x4 + (size_t)n * 32 + lane);
    int j = beg;
    for (; j + 8 <= end; j += 8) {
        int idx[8];
#pragma unroll
        for (int t = 0; t < 8; t++) idx[t] = __ldg(g_csr + j + t);
        float4 v[8];
#pragma unroll
        for (int t = 0; t < 8; t++) v[t] = __ldg(x4 + (size_t)idx[t] * 32 + lane);
#pragma unroll
        for (int t = 0; t < 8; t++) {
            acc.x += v[t].x; acc.y += v[t].y; acc.z += v[t].z; acc.w += v[t].w;
        }
    }
    for (; j < end; j++) {
        int s = __ldg(g_csr + j);
        float4 v = __ldg(x4 + (size_t)s * 32 + lane);
        acc.x += v.x; acc.y += v.y; acc.z += v.z; acc.w += v.w;
    }
    ((float4*)g_aggr)[(size_t)n * 32 + lane] = acc;
}

// ===================== register-tiled GEMM =====================
// block: 256 threads, tile 64 nodes x 128 cols.
// thread: tc = t&7 (cols tc*16..tc*16+15), tr = t>>3 (nodes tr*2, tr*2+1)
// W smem layout (swizzled, per k-row of 512B): 16B chunk for (j, tc) at
// chunk index j*8 + tc, holding cols tc*16 + j*4 .. +3.  -> conflict-free LDS.128
// A smem: ins[64][130] (pad 130 keeps float2 k-pairs 8B aligned)

#define INS_STRIDE 130

// prologue: load W [128x128] row-major -> swizzled smem
__device__ __forceinline__ void load_W_swz(const float* __restrict__ W, float* __restrict__ Ws, int tid) {
    for (int i = tid; i < 4096; i += 256) {
        float4 v = __ldg((const float4*)W + i);
        int k = i >> 5, c4 = i & 31;
        ((float4*)Ws)[k * 32 + ((c4 & 3) * 8 + (c4 >> 2))] = v;
    }
}

// prologue: 64 node rows -> ins[64][130]
__device__ __forceinline__ void load_rows(const float* __restrict__ src, int node0,
                                          float* __restrict__ ins, int tid) {
    for (int i = tid; i < 2048; i += 256) {
        int n = i >> 5, q = i & 31;
        int node = node0 + n;
        if (node > N_NODES - 1) node = N_NODES - 1;
        float4 a = __ldg((const float4*)src + (size_t)node * 32 + q);
        float* p = ins + n * INS_STRIDE + q * 4;
        ((float2*)p)[0] = make_float2(a.x, a.y);
        ((float2*)p)[1] = make_float2(a.z, a.w);
    }
}

// core: acc[i*8 + j*2 + p] : node i (0..1), col group j (0..3), pair p
__device__ __forceinline__ void gemm_core(const float* __restrict__ ins,
                                          const float* __restrict__ Ws,
                                          int tc, int tr, unsigned long long acc[16]) {
#pragma unroll
    for (int q = 0; q < 16; q++) acc[q] = 0ULL;
    const float* arow = ins + (tr * 2) * INS_STRIDE;
#pragma unroll 2
    for (int k = 0; k < 128; k += 2) {
        float2 a0 = *(const float2*)(arow + k);
        float2 a1 = *(const float2*)(arow + INS_STRIDE + k);
        unsigned long long a00 = pack2(a0.x, a0.x), a01 = pack2(a0.y, a0.y);
        unsigned long long a10 = pack2(a1.x, a1.x), a11 = pack2(a1.y, a1.y);
        const float* wk0 = Ws + k * 128 + tc * 4;
        const float* wk1 = wk0 + 128;
#pragma unroll
        for (int j = 0; j < 4; j++) {
            ulonglong2 w0 = *(const ulonglong2*)(wk0 + j * 32);
            ulonglong2 w1 = *(const ulonglong2*)(wk1 + j * 32);
            ffma2(acc[j * 2], a00, w0.x);     ffma2(acc[j * 2 + 1], a00, w0.y);
            ffma2(acc[8 + j * 2], a10, w0.x); ffma2(acc[8 + j * 2 + 1], a10, w0.y);
            ffma2(acc[j * 2], a01, w1.x);     ffma2(acc[j * 2 + 1], a01, w1.y);
            ffma2(acc[8 + j * 2], a11, w1.x); ffma2(acc[8 + j * 2 + 1], a11, w1.y);
        }
    }
}

// -------- MLP1: h1 = relu(BN(aggr @ W1)) --------
__global__ __launch_bounds__(256) void k_mlp1(const float* __restrict__ W1,
                                              const float* __restrict__ b1,
                                              const float* __restrict__ gamma,
                                              const float* __restrict__ beta,
                                              const float* __restrict__ rmean,
                                              const float* __restrict__ rvar) {
    extern __shared__ float sm[];
    float* Ws = sm;                         // 16384
    float* ins = Ws + 16384;                // 64*130 = 8320
    float* scale_s = ins + 64 * INS_STRIDE; // 128
    float* shift_s = scale_s + 128;         // 128
    int tid = threadIdx.x;
    load_W_swz(W1, Ws, tid);
    if (tid < 128) {
        float sc = gamma[tid] * rsqrtf(rvar[tid] + 1e-5f);
        scale_s[tid] = sc;
        shift_s[tid] = (b1[tid] - rmean[tid]) * sc + beta[tid];
    }
    int node0 = blockIdx.x << 6;
    load_rows(g_aggr, node0, ins, tid);
    __syncthreads();

    int tc = tid & 7, tr = tid >> 3;
    unsigned long long acc[16];
    gemm_core(ins, Ws, tc, tr, acc);

#pragma unroll
    for (int i = 0; i < 2; i++) {
        int node = node0 + tr * 2 + i;
        if (node >= N_NODES) break;
#pragma unroll
        for (int j = 0; j < 4; j++) {
            int c0 = tc * 16 + j * 4;
            float2 f0 = unpack2(acc[i * 8 + j * 2]);
            float2 f1 = unpack2(acc[i * 8 + j * 2 + 1]);
            float4 r;
            r.x = fmaxf(f0.x * scale_s[c0 + 0] + shift_s[c0 + 0], 0.f);
            r.y = fmaxf(f0.y * scale_s[c0 + 1] + shift_s[c0 + 1], 0.f);
            r.z = fmaxf(f1.x * scale_s[c0 + 2] + shift_s[c0 + 2], 0.f);
            r.w = fmaxf(f1.y * scale_s[c0 + 3] + shift_s[c0 + 3], 0.f);
            *(float4*)(g_h1 + (size_t)node * 128 + c0) = r;
        }
    }
}

// -------- MLP2: h2 = relu(h1 @ W2 + b2), in place --------
__global__ __launch_bounds__(256) void k_mlp2(const float* __restrict__ W2,
                                              const float* __restrict__ b2) {
    extern __shared__ float sm[];
    float* Ws = sm;
    float* ins = Ws + 16384;
    float* bs = ins + 64 * INS_STRIDE;
    int tid = threadIdx.x;
    load_W_swz(W2, Ws, tid);
    if (tid < 128) bs[tid] = b2[tid];
    int node0 = blockIdx.x << 6;
    load_rows(g_h1, node0, ins, tid);
    __syncthreads();

    int tc = tid & 7, tr = tid >> 3;
    unsigned long long acc[16];
    gemm_core(ins, Ws, tc, tr, acc);

#pragma unroll
    for (int i = 0; i < 2; i++) {
        int node = node0 + tr * 2 + i;
        if (node >= N_NODES) break;
#pragma unroll
        for (int j = 0; j < 4; j++) {
            int c0 = tc * 16 + j * 4;
            float2 f0 = unpack2(acc[i * 8 + j * 2]);
            float2 f1 = unpack2(acc[i * 8 + j * 2 + 1]);
            float4 r;
            r.x = fmaxf(f0.x + bs[c0 + 0], 0.f);
            r.y = fmaxf(f0.y + bs[c0 + 1], 0.f);
            r.z = fmaxf(f1.x + bs[c0 + 2], 0.f);
            r.w = fmaxf(f1.y + bs[c0 + 3], 0.f);
            *(float4*)(g_h1 + (size_t)node * 128 + c0) = r;
        }
    }
}

// -------- MLP3: xw = h2 @ [Wmu|Wls]; xws = dinv*xw; out = dinv*xws + b -----
__global__ __launch_bounds__(256) void k_mlp3(const float* __restrict__ Wmu,
                                              const float* __restrict__ bmu,
                                              const float* __restrict__ Wls,
                                              const float* __restrict__ bls,
                                              float* __restrict__ out) {
    extern __shared__ float sm[];
    float* Ws = sm;
    float* ins = Ws + 16384;
    float* bs = ins + 64 * INS_STRIDE;
    int tid = threadIdx.x;
    for (int i = tid; i < 4096; i += 256) {
        int k = i >> 5, c4 = i & 31;
        float4 v = (c4 < 16) ? __ldg((const float4*)Wmu + k * 16 + c4)
                             : __ldg((const float4*)Wls + k * 16 + (c4 - 16));
        ((float4*)Ws)[k * 32 + ((c4 & 3) * 8 + (c4 >> 2))] = v;
    }
    if (tid < 128) bs[tid] = (tid < 64) ? bmu[tid] : bls[tid - 64];
    int node0 = blockIdx.x << 6;
    load_rows(g_h1, node0, ins, tid);
    __syncthreads();

    int tc = tid & 7, tr = tid >> 3;
    unsigned long long acc[16];
    gemm_core(ins, Ws, tc, tr, acc);

#pragma unroll
    for (int i = 0; i < 2; i++) {
        int node = node0 + tr * 2 + i;
        if (node >= N_NODES) break;
        float dn = g_dinv[node];
#pragma unroll
        for (int j = 0; j < 4; j++) {
            int c0 = tc * 16 + j * 4;
            float2 f0 = unpack2(acc[i * 8 + j * 2]);
            float2 f1 = unpack2(acc[i * 8 + j * 2 + 1]);
            float4 xs = make_float4(dn * f0.x, dn * f0.y, dn * f1.x, dn * f1.y);
            *(float4*)(g_xw + (size_t)node * 128 + c0) = xs;
            float4 ov;
            ov.x = dn * xs.x + bs[c0 + 0];
            ov.y = dn * xs.y + bs[c0 + 1];
            ov.z = dn * xs.z + bs[c0 + 2];
            ov.w = dn * xs.w + bs[c0 + 3];
            float* ob = (c0 < 64) ? (out + (size_t)node * 64 + c0)
                                  : (out + (size_t)N_NODES * 64 + (size_t)node * 64 + (c0 - 64));
            *(float4*)ob = ov;
        }
    }
}

// -------- GCN gather: out[n] += dinv[n] * sum xws[csr]  (warp/node, 8-deep) --
__global__ __launch_bounds__(256) void k_gcn_gather(float* __restrict__ out) {
    int n = blockIdx.x * 8 + (threadIdx.x >> 5);
    if (n >= N_NODES) return;
    int lane = threadIdx.x & 31;
    int beg = __ldg(g_off + n), end = __ldg(g_off + n + 1);
    const float4* xw4 = (const float4*)g_xw;
    float4 acc = make_float4(0.f, 0.f, 0.f, 0.f);
    int j = beg;
    for (; j + 8 <= end; j += 8) {
        int idx[8];
#pragma unroll
        for (int t = 0; t < 8; t++) idx[t] = __ldg(g_csr + j + t);
        float4 v[8];
#pragma unroll
        for (int t = 0; t < 8; t++) v[t] = __ldg(xw4 + (size_t)idx[t] * 32 + lane);
#pragma unroll
        for (int t = 0; t < 8; t++) {
            acc.x += v[t].x; acc.y += v[t].y; acc.z += v[t].z; acc.w += v[t].w;
        }
    }
    for (; j < end; j++) {
        int s = __ldg(g_csr + j);
        float4 v = __ldg(xw4 + (size_t)s * 32 + lane);
        acc.x += v.x; acc.y += v.y; acc.z += v.z; acc.w += v.w;
    }
    float dn = g_dinv[n];
    int c0 = lane * 4;
    float* ob = (c0 < 64) ? (out + (size_t)n * 64 + c0)
                          : (out + (size_t)N_NODES * 64 + (size_t)n * 64 + (c0 - 64));
    float4 cur = *(float4*)ob;
    cur.x += dn * acc.x; cur.y += dn * acc.y;
    cur.z += dn * acc.z; cur.w += dn * acc.w;
    *(float4*)ob = cur;
}

extern "C" void kernel_launch(void* const* d_in, const int* in_sizes, int n_in,
                              void* d_out, int out_size) {
    const float* x     = (const float*)d_in[0];
    const void*  ei    = (const void*)d_in[1];
    const float* W1    = (const float*)d_in[2];
    const float* b1    = (const float*)d_in[3];
    const float* gamma = (const float*)d_in[4];
    const float* beta  = (const float*)d_in[5];
    const float* rmean = (const float*)d_in[6];
    const float* rvar  = (const float*)d_in[7];
    const float* W2    = (const float*)d_in[8];
    const float* b2    = (const float*)d_in[9];
    const float* Wmu   = (const float*)d_in[10];
    const float* bmu   = (const float*)d_in[11];
    const float* Wls   = (const float*)d_in[12];
    const float* bls   = (const float*)d_in[13];
    float* out = (float*)d_out;

    int E = in_sizes[1] / 2;

    const int SMEM = (16384 + 64 * INS_STRIDE + 256) * 4;  // 99840 B
    cudaFuncSetAttribute(k_mlp1, cudaFuncAttributeMaxDynamicSharedMemorySize, SMEM);
    cudaFuncSetAttribute(k_mlp2, cudaFuncAttributeMaxDynamicSharedMemorySize, SMEM);
    cudaFuncSetAttribute(k_mlp3, cudaFuncAttributeMaxDynamicSharedMemorySize, SMEM);

    int eb = (E + 255) / 256;
    int nb = (N_NODES + 7) / 8;
    int mb = (N_NODES + 63) / 64;

    k_zero<<<(N_NODES + 255) / 256, 256>>>();
    k_count<<<eb, 256>>>(ei, E);
    k_scan<<<1, 1024>>>();
    k_fill<<<eb, 256>>>(E);
    k_gin_gather<<<nb, 256>>>(x);
    k_mlp1<<<mb, 256, SMEM>>>(W1, b1, gamma, beta, rmean, rvar);
    k_mlp2<<<mb, 256, SMEM>>>(W2, b2);
    k_mlp3<<<mb, 256, SMEM>>>(Wmu, bmu, Wls, bls, out);
    k_gcn_gather<<<nb, 256>>>(out);
}

// round 6
// speedup vs baseline: 4.2290x; 1.0343x over previous
#include <cuda_runtime.h>
#include <cuda_fp16.h>
#include <cstdint>

#define N_NODES 100000
#define DIMH 128
#define E_CAP 4000000

// -------- scratch (device globals; no allocation allowed) --------
__device__ __align__(16) float  g_aggr[(size_t)N_NODES * DIMH];
__device__ __align__(16) float  g_h1[(size_t)N_NODES * DIMH];
__device__ __align__(16) __half g_xh[(size_t)N_NODES * DIMH];   // fp16 copy of x
__device__ __align__(16) __half g_xwh[(size_t)N_NODES * DIMH];  // fp16 dinv-scaled xw
__device__ float g_dinv[N_NODES];
__device__ int   g_deg[N_NODES];   // zero-initialized at load; k_fill re-zeros each call
__device__ int   g_off[N_NODES + 1];
__device__ int   g_cur[N_NODES];
__device__ int   g_csr[E_CAP];
__device__ int2  g_edge[E_CAP];

// -------- packed f32x2 helpers --------
__device__ __forceinline__ unsigned long long pack2(float a, float b) {
    unsigned long long r;
    asm("mov.b64 %0, {%1,%2};" : "=l"(r) : "f"(a), "f"(b));
    return r;
}
__device__ __forceinline__ void ffma2(unsigned long long& d, unsigned long long a, unsigned long long b) {
    asm("fma.rn.f32x2 %0, %1, %2, %0;" : "+l"(d) : "l"(a), "l"(b));
}
__device__ __forceinline__ float2 unpack2(unsigned long long v) {
    float2 r;
    asm("mov.b64 {%0,%1}, %2;" : "=f"(r.x), "=f"(r.y) : "l"(v));
    return r;
}

// -------- count + edge conversion + x->fp16 (per-block dtype detect) --------
__global__ __launch_bounds__(256) void k_count(const void* __restrict__ ei,
                                               const float* __restrict__ x, int E) {
    __shared__ int s_is64;
    if (threadIdx.x < 32) {
        unsigned w = __ldg((const unsigned*)ei + threadIdx.x * 2 + 1);
        unsigned b = __ballot_sync(0xffffffffu, w != 0u);
        if (threadIdx.x == 0) s_is64 = (b == 0u);
    }
    __syncthreads();
    int gid = blockIdx.x * 256 + threadIdx.x;
    int total = gridDim.x * 256;
    if (gid < E) {
        int s, d;
        if (s_is64) {
            s = (int)__ldg((const long long*)ei + gid);
            d = (int)__ldg((const long long*)ei + E + gid);
        } else {
            s = __ldg((const int*)ei + gid);
            d = __ldg((const int*)ei + E + gid);
        }
        g_edge[gid] = make_int2(s, d);
        atomicAdd(&g_deg[d], 1);
    }
    // convert x (fp32) -> g_xh (fp16), grid-stride over float2 elements
    const float2* x2 = (const float2*)x;
    __half2* xh2 = (__half2*)g_xh;
    const int NH2 = N_NODES * (DIMH / 2);
    for (int i = gid; i < NH2; i += total) {
        float2 v = __ldg(x2 + i);
        xh2[i] = __floats2half2_rn(v.x, v.y);
    }
}

// -------- coalesced tiled single-block scan (+ dinv) --------
__global__ __launch_bounds__(1024) void k_scan() {
    __shared__ int wsum[32];
    __shared__ int s_carry;
    int tid = threadIdx.x, lane = tid & 31, wid = tid >> 5;
    if (tid == 0) s_carry = 0;
    __syncthreads();
    const int NT = (N_NODES + 1023) / 1024;  // 98
    for (int t = 0; t < NT; t++) {
        int idx = t * 1024 + tid;
        int dg = (idx < N_NODES) ? g_deg[idx] : 0;
        int v = dg;
#pragma unroll
        for (int o = 1; o < 32; o <<= 1) {
            int u = __shfl_up_sync(~0u, v, o);
            if (lane >= o) v += u;
        }
        if (lane == 31) wsum[wid] = v;
        __syncthreads();
        if (wid == 0) {
            int w = wsum[lane];
#pragma unroll
            for (int o = 1; o < 32; o <<= 1) {
                int u = __shfl_up_sync(~0u, w, o);
                if (lane >= o) w += u;
            }
            wsum[lane] = w;
        }
        __syncthreads();
        int excl = v - dg + ((wid > 0) ? wsum[wid - 1] : 0) + s_carry;
        if (idx < N_NODES) {
            g_off[idx] = excl;
            g_cur[idx] = excl;
            g_dinv[idx] = rsqrtf((float)dg + 1.0f);
        }
        __syncthreads();
        if (tid == 0) s_carry += wsum[31];
        __syncthreads();
    }
    if (tid == 0) g_off[N_NODES] = s_carry;
}

// -------- fill CSR; also re-zero g_deg for the next call --------
__global__ __launch_bounds__(256) void k_fill(int E) {
    int e = blockIdx.x * 256 + threadIdx.x;
    int total = gridDim.x * 256;
    if (e < E) {
        int2 sd = g_edge[e];
        int pos = atomicAdd(&g_cur[sd.y], 1);
        g_csr[pos] = sd.x;
    }
    for (int i = e; i < N_NODES; i += total) g_deg[i] = 0;
}

// -------- GIN gather (fp16 rows): aggr[n] = x[n] + sum xh[csr] ------------
__global__ __launch_bounds__(256) void k_gin_gather(const float* __restrict__ x) {
    int n = blockIdx.x * 8 + (threadIdx.x >> 5);
    if (n >= N_NODES) return;
    int lane = threadIdx.x & 31;
    int beg = __ldg(g_off + n), end = __ldg(g_off + n + 1);
    const uint2* xh = (const uint2*)g_xh;  // 8B = 4 halfs per lane
    float4 a0 = __ldg((const float4*)x + (size_t)n * 32 + lane);  // self (fp32)
    float2 accA = make_float2(a0.x, a0.y);
    float2 accB = make_float2(a0.z, a0.w);
    int j = beg;
    for (; j + 8 <= end; j += 8) {
        int idx[8];
#pragma unroll
        for (int t = 0; t < 8; t++) idx[t] = __ldg(g_csr + j + t);
        uint2 v[8];
#pragma unroll
        for (int t = 0; t < 8; t++) v[t] = __ldg(xh + (size_t)idx[t] * 32 + lane);
#pragma unroll
        for (int t = 0; t < 8; t++) {
            float2 f0 = __half22float2(*(__half2*)&v[t].x);
            float2 f1 = __half22float2(*(__half2*)&v[t].y);
            accA.x += f0.x; accA.y += f0.y;
            accB.x += f1.x; accB.y += f1.y;
        }
    }
    for (; j < end; j++) {
        int s = __ldg(g_csr + j);
        uint2 v = __ldg(xh + (size_t)s * 32 + lane);
        float2 f0 = __half22float2(*(__half2*)&v.x);
        float2 f1 = __half22float2(*(__half2*)&v.y);
        accA.x += f0.x; accA.y += f0.y;
        accB.x += f1.x; accB.y += f1.y;
    }
    ((float4*)g_aggr)[(size_t)n * 32 + lane] = make_float4(accA.x, accA.y, accB.x, accB.y);
}

// ===================== register-tiled GEMM =====================
#define INS_STRIDE 130

__device__ __forceinline__ void load_W_swz(const float* __restrict__ W, float* __restrict__ Ws, int tid) {
    for (int i = tid; i < 4096; i += 256) {
        float4 v = __ldg((const float4*)W + i);
        int k = i >> 5, c4 = i & 31;
        ((float4*)Ws)[k * 32 + ((c4 & 3) * 8 + (c4 >> 2))] = v;
    }
}

__device__ __forceinline__ void load_rows(const float* __restrict__ src, int node0,
                                          float* __restrict__ ins, int tid) {
    for (int i = tid; i < 2048; i += 256) {
        int n = i >> 5, q = i & 31;
        int node = node0 + n;
        if (node > N_NODES - 1) node = N_NODES - 1;
        float4 a = __ldg((const float4*)src + (size_t)node * 32 + q);
        float* p = ins + n * INS_STRIDE + q * 4;
        ((float2*)p)[0] = make_float2(a.x, a.y);
        ((float2*)p)[1] = make_float2(a.z, a.w);
    }
}

__device__ __forceinline__ void gemm_core(const float* __restrict__ ins,
                                          const float* __restrict__ Ws,
                                          int tc, int tr, unsigned long long acc[16]) {
#pragma unroll
    for (int q = 0; q < 16; q++) acc[q] = 0ULL;
    const float* arow = ins + (tr * 2) * INS_STRIDE;
#pragma unroll 2
    for (int k = 0; k < 128; k += 2) {
        float2 a0 = *(const float2*)(arow + k);
        float2 a1 = *(const float2*)(arow + INS_STRIDE + k);
        unsigned long long a00 = pack2(a0.x, a0.x), a01 = pack2(a0.y, a0.y);
        unsigned long long a10 = pack2(a1.x, a1.x), a11 = pack2(a1.y, a1.y);
        const float* wk0 = Ws + k * 128 + tc * 4;
        const float* wk1 = wk0 + 128;
#pragma unroll
        for (int j = 0; j < 4; j++) {
            ulonglong2 w0 = *(const ulonglong2*)(wk0 + j * 32);
            ulonglong2 w1 = *(const ulonglong2*)(wk1 + j * 32);
            ffma2(acc[j * 2], a00, w0.x);     ffma2(acc[j * 2 + 1], a00, w0.y);
            ffma2(acc[8 + j * 2], a10, w0.x); ffma2(acc[8 + j * 2 + 1], a10, w0.y);
            ffma2(acc[j * 2], a01, w1.x);     ffma2(acc[j * 2 + 1], a01, w1.y);
            ffma2(acc[8 + j * 2], a11, w1.x); ffma2(acc[8 + j * 2 + 1], a11, w1.y);
        }
    }
}

// -------- MLP1: h1 = relu(BN(aggr @ W1)) --------
__global__ __launch_bounds__(256) void k_mlp1(const float* __restrict__ W1,
                                              const float* __restrict__ b1,
                                              const float* __restrict__ gamma,
                                              const float* __restrict__ beta,
                                              const float* __restrict__ rmean,
                                              const float* __restrict__ rvar) {
    extern __shared__ float sm[];
    float* Ws = sm;
    float* ins = Ws + 16384;
    float* scale_s = ins + 64 * INS_STRIDE;
    float* shift_s = scale_s + 128;
    int tid = threadIdx.x;
    load_W_swz(W1, Ws, tid);
    if (tid < 128) {
        float sc = gamma[tid] * rsqrtf(rvar[tid] + 1e-5f);
        scale_s[tid] = sc;
        shift_s[tid] = (b1[tid] - rmean[tid]) * sc + beta[tid];
    }
    int node0 = blockIdx.x << 6;
    load_rows(g_aggr, node0, ins, tid);
    __syncthreads();

    int tc = tid & 7, tr = tid >> 3;
    unsigned long long acc[16];
    gemm_core(ins, Ws, tc, tr, acc);

#pragma unroll
    for (int i = 0; i < 2; i++) {
        int node = node0 + tr * 2 + i;
        if (node >= N_NODES) break;
#pragma unroll
        for (int j = 0; j < 4; j++) {
            int c0 = tc * 16 + j * 4;
            float2 f0 = unpack2(acc[i * 8 + j * 2]);
            float2 f1 = unpack2(acc[i * 8 + j * 2 + 1]);
            float4 r;
            r.x = fmaxf(f0.x * scale_s[c0 + 0] + shift_s[c0 + 0], 0.f);
            r.y = fmaxf(f0.y * scale_s[c0 + 1] + shift_s[c0 + 1], 0.f);
            r.z = fmaxf(f1.x * scale_s[c0 + 2] + shift_s[c0 + 2], 0.f);
            r.w = fmaxf(f1.y * scale_s[c0 + 3] + shift_s[c0 + 3], 0.f);
            *(float4*)(g_h1 + (size_t)node * 128 + c0) = r;
        }
    }
}

// -------- MLP2: h2 = relu(h1 @ W2 + b2), in place --------
__global__ __launch_bounds__(256) void k_mlp2(const float* __restrict__ W2,
                                              const float* __restrict__ b2) {
    extern __shared__ float sm[];
    float* Ws = sm;
    float* ins = Ws + 16384;
    float* bs = ins + 64 * INS_STRIDE;
    int tid = threadIdx.x;
    load_W_swz(W2, Ws, tid);
    if (tid < 128) bs[tid] = b2[tid];
    int node0 = blockIdx.x << 6;
    load_rows(g_h1, node0, ins, tid);
    __syncthreads();

    int tc = tid & 7, tr = tid >> 3;
    unsigned long long acc[16];
    gemm_core(ins, Ws, tc, tr, acc);

#pragma unroll
    for (int i = 0; i < 2; i++) {
        int node = node0 + tr * 2 + i;
        if (node >= N_NODES) break;
#pragma unroll
        for (int j = 0; j < 4; j++) {
            int c0 = tc * 16 + j * 4;
            float2 f0 = unpack2(acc[i * 8 + j * 2]);
            float2 f1 = unpack2(acc[i * 8 + j * 2 + 1]);
            float4 r;
            r.x = fmaxf(f0.x + bs[c0 + 0], 0.f);
            r.y = fmaxf(f0.y + bs[c0 + 1], 0.f);
            r.z = fmaxf(f1.x + bs[c0 + 2], 0.f);
            r.w = fmaxf(f1.y + bs[c0 + 3], 0.f);
            *(float4*)(g_h1 + (size_t)node * 128 + c0) = r;
        }
    }
}

// -------- MLP3: xw = h2 @ [Wmu|Wls]; xwh = half(dinv*xw); out = dinv^2*xw + b
__global__ __launch_bounds__(256) void k_mlp3(const float* __restrict__ Wmu,
                                              const float* __restrict__ bmu,
                                              const float* __restrict__ Wls,
                                              const float* __restrict__ bls,
                                              float* __restrict__ out) {
    extern __shared__ float sm[];
    float* Ws = sm;
    float* ins = Ws + 16384;
    float* bs = ins + 64 * INS_STRIDE;
    int tid = threadIdx.x;
    for (int i = tid; i < 4096; i += 256) {
        int k = i >> 5, c4 = i & 31;
        float4 v = (c4 < 16) ? __ldg((const float4*)Wmu + k * 16 + c4)
                             : __ldg((const float4*)Wls + k * 16 + (c4 - 16));
        ((float4*)Ws)[k * 32 + ((c4 & 3) * 8 + (c4 >> 2))] = v;
    }
    if (tid < 128) bs[tid] = (tid < 64) ? bmu[tid] : bls[tid - 64];
    int node0 = blockIdx.x << 6;
    load_rows(g_h1, node0, ins, tid);
    __syncthreads();

    int tc = tid & 7, tr = tid >> 3;
    unsigned long long acc[16];
    gemm_core(ins, Ws, tc, tr, acc);

#pragma unroll
    for (int i = 0; i < 2; i++) {
        int node = node0 + tr * 2 + i;
        if (node >= N_NODES) break;
        float dn = g_dinv[node];
#pragma unroll
        for (int j = 0; j < 4; j++) {
            int c0 = tc * 16 + j * 4;
            float2 f0 = unpack2(acc[i * 8 + j * 2]);
            float2 f1 = unpack2(acc[i * 8 + j * 2 + 1]);
            float4 xs = make_float4(dn * f0.x, dn * f0.y, dn * f1.x, dn * f1.y);
            uint2 hx;
            *(__half2*)&hx.x = __floats2half2_rn(xs.x, xs.y);
            *(__half2*)&hx.y = __floats2half2_rn(xs.z, xs.w);
            *(uint2*)(g_xwh + (size_t)node * 128 + c0) = hx;
            float4 ov;
            ov.x = dn * xs.x + bs[c0 + 0];
            ov.y = dn * xs.y + bs[c0 + 1];
            ov.z = dn * xs.z + bs[c0 + 2];
            ov.w = dn * xs.w + bs[c0 + 3];
            float* ob = (c0 < 64) ? (out + (size_t)node * 64 + c0)
                                  : (out + (size_t)N_NODES * 64 + (size_t)node * 64 + (c0 - 64));
            *(float4*)ob = ov;
        }
    }
}

// -------- GCN gather (fp16 rows): out[n] += dinv[n] * sum xwh[csr] ---------
__global__ __launch_bounds__(256) void k_gcn_gather(float* __restrict__ out) {
    int n = blockIdx.x * 8 + (threadIdx.x >> 5);
    if (n >= N_NODES) return;
    int lane = threadIdx.x & 31;
    int beg = __ldg(g_off + n), end = __ldg(g_off + n + 1);
    const uint2* xh = (const uint2*)g_xwh;
    float2 accA = make_float2(0.f, 0.f), accB = make_float2(0.f, 0.f);
    int j = beg;
    for (; j + 8 <= end; j += 8) {
        int idx[8];
#pragma unroll
        for (int t = 0; t < 8; t++) idx[t] = __ldg(g_csr + j + t);
        uint2 v[8];
#pragma unroll
        for (int t = 0; t < 8; t++) v[t] = __ldg(xh + (size_t)idx[t] * 32 + lane);
#pragma unroll
        for (int t = 0; t < 8; t++) {
            float2 f0 = __half22float2(*(__half2*)&v[t].x);
            float2 f1 = __half22float2(*(__half2*)&v[t].y);
            accA.x += f0.x; accA.y += f0.y;
            accB.x += f1.x; accB.y += f1.y;
        }
    }
    for (; j < end; j++) {
        int s = __ldg(g_csr + j);
        uint2 v = __ldg(xh + (size_t)s * 32 + lane);
        float2 f0 = __half22float2(*(__half2*)&v.x);
        float2 f1 = __half22float2(*(__half2*)&v.y);
        accA.x += f0.x; accA.y += f0.y;
        accB.x += f1.x; accB.y += f1.y;
    }
    float dn = g_dinv[n];
    int c0 = lane * 4;
    float* ob = (c0 < 64) ? (out + (size_t)n * 64 + c0)
                          : (out + (size_t)N_NODES * 64 + (size_t)n * 64 + (c0 - 64));
    float4 cur = *(float4*)ob;
    cur.x += dn * accA.x; cur.y += dn * accA.y;
    cur.z += dn * accB.x; cur.w += dn * accB.y;
    *(float4*)ob = cur;
}

extern "C" void kernel_launch(void* const* d_in, const int* in_sizes, int n_in,
                              void* d_out, int out_size) {
    const float* x     = (const float*)d_in[0];
    const void*  ei    = (const void*)d_in[1];
    const float* W1    = (const float*)d_in[2];
    const float* b1    = (const float*)d_in[3];
    const float* gamma = (const float*)d_in[4];
    const float* beta  = (const float*)d_in[5];
    const float* rmean = (const float*)d_in[6];
    const float* rvar  = (const float*)d_in[7];
    const float* W2    = (const float*)d_in[8];
    const float* b2    = (const float*)d_in[9];
    const float* Wmu   = (const float*)d_in[10];
    const float* bmu   = (const float*)d_in[11];
    const float* Wls   = (const float*)d_in[12];
    const float* bls   = (const float*)d_in[13];
    float* out = (float*)d_out;

    int E = in_sizes[1] / 2;

    const int SMEM = (16384 + 64 * INS_STRIDE + 256) * 4;  // 99840 B
    cudaFuncSetAttribute(k_mlp1, cudaFuncAttributeMaxDynamicSharedMemorySize, SMEM);
    cudaFuncSetAttribute(k_mlp2, cudaFuncAttributeMaxDynamicSharedMemorySize, SMEM);
    cudaFuncSetAttribute(k_mlp3, cudaFuncAttributeMaxDynamicSharedMemorySize, SMEM);

    int eb = (E + 255) / 256;
    int nb = (N_NODES + 7) / 8;
    int mb = (N_NODES + 63) / 64;

    k_count<<<eb, 256>>>(ei, x, E);          // 0
    k_scan<<<1, 1024>>>();                   // 1
    k_fill<<<eb, 256>>>(E);                  // 2
    k_gin_gather<<<nb, 256>>>(x);            // 3  <- profiled slot
    k_mlp1<<<mb, 256, SMEM>>>(W1, b1, gamma, beta, rmean, rvar);
    k_mlp2<<<mb, 256, SMEM>>>(W2, b2);
    k_mlp3<<<mb, 256, SMEM>>>(Wmu, bmu, Wls, bls, out);
    k_gcn_gather<<<nb, 256>>>(out);
}